// round 2
// baseline (speedup 1.0000x reference)
#include <cuda_runtime.h>
#include <cstring>

#define BB    2048
#define CIN   256
#define LIN   256
#define COUT  64
#define KSZ   16
#define LOUTD 61
#define FLATD 3904   // 64*61
#define H1D   512
#define H2D   128

// ---- scratch (device globals; no allocation allowed) ----
__device__ float g_weff[COUT * CIN * KSZ];        // BN-folded conv weights [co][ci][k]
__device__ float g_cbias[COUT];                   // BN-folded conv bias
__device__ float g_Wc[H2D * FLATD];               // fc2_w @ fc1_w   [128][3904]
__device__ float g_bc[H2D];                       // fc2_w @ fc1_b + fc2_b
__device__ float g_z[(size_t)BB * FLATD];         // conv+relu output [B][3904]

// packed fp32x2 FMA (FFMA2) — ptxas will not emit this from C++; PTX-only
#define FMA2(acc, a, b) asm("fma.rn.f32x2 %0, %1, %2, %0;" : "+l"(acc) : "l"(a), "l"(b))

// ---------------------------------------------------------------------------
// Prep 1: fold BN into conv weights/bias
// ---------------------------------------------------------------------------
__global__ void prep_conv(const float* __restrict__ w, const float* __restrict__ cb,
                          const float* __restrict__ gamma, const float* __restrict__ beta,
                          const float* __restrict__ mean, const float* __restrict__ var) {
    int idx = blockIdx.x * blockDim.x + threadIdx.x;
    if (idx < COUT * CIN * KSZ) {
        int co = idx / (CIN * KSZ);
        float inv = gamma[co] * rsqrtf(var[co] + 1e-5f);
        g_weff[idx] = w[idx] * inv;
    }
    if (idx < COUT) {
        float inv = gamma[idx] * rsqrtf(var[idx] + 1e-5f);
        g_cbias[idx] = (cb[idx] - mean[idx]) * inv + beta[idx];
    }
}

// ---------------------------------------------------------------------------
// Prep 2: Wc[i][j] = sum_h fc2_w[i][h] * fc1_w[h][j]   (128 x 3904, K=512)
// grid (61, 2), block 256; block tile 64j x 64i, thread tile 4x4
// ---------------------------------------------------------------------------
__global__ __launch_bounds__(256) void combine_fc(const float* __restrict__ f1w,
                                                  const float* __restrict__ f2w) {
    __shared__ __align__(16) float a_s[64][33];  // fc2 tile [i][h]
    __shared__ __align__(16) float b_s[32][68];  // fc1 tile [h][j]
    int j0 = blockIdx.x * 64, i0 = blockIdx.y * 64;
    int tid = threadIdx.x, tx = tid & 15, ty = tid >> 4;
    float acc[4][4] = {};
    for (int h0 = 0; h0 < H1D; h0 += 32) {
        for (int g = tid; g < 2048; g += 256) {
            int r = g >> 5, c = g & 31;
            a_s[r][c] = f2w[(size_t)(i0 + r) * H1D + h0 + c];
        }
        for (int g = tid; g < 512; g += 256) {
            int r = g >> 4, c4 = g & 15;
            *(float4*)&b_s[r][c4 * 4] =
                *(const float4*)(f1w + (size_t)(h0 + r) * FLATD + j0 + c4 * 4);
        }
        __syncthreads();
        #pragma unroll
        for (int h = 0; h < 32; h++) {
            float av[4], bv[4];
            #pragma unroll
            for (int iq = 0; iq < 4; iq++) av[iq] = a_s[ty * 4 + iq][h];
            #pragma unroll
            for (int jq = 0; jq < 4; jq++) bv[jq] = b_s[h][tx * 4 + jq];
            #pragma unroll
            for (int iq = 0; iq < 4; iq++)
                #pragma unroll
                for (int jq = 0; jq < 4; jq++) acc[iq][jq] += av[iq] * bv[jq];
        }
        __syncthreads();
    }
    #pragma unroll
    for (int iq = 0; iq < 4; iq++)
        #pragma unroll
        for (int jq = 0; jq < 4; jq++)
            g_Wc[(size_t)(i0 + ty * 4 + iq) * FLATD + j0 + tx * 4 + jq] = acc[iq][jq];
}

__global__ void bias_fc(const float* __restrict__ f2w, const float* __restrict__ f1b,
                        const float* __restrict__ f2b) {
    int i = threadIdx.x;  // 128 threads
    float s = f2b[i];
    for (int h = 0; h < H1D; h++) s += f2w[(size_t)i * H1D + h] * f1b[h];
    g_bc[i] = s;
}

// ---------------------------------------------------------------------------
// Conv1d(256->64, k16, s4) + bias + relu -> g_z[b][co*61+l]
// 1 block per batch sample. 256 thr (tx=l-tile, ty=co-tile), thread = 4co x 4l.
// K-packed FFMA2: acc2 += (x[4l+2k2], x[4l+2k2+1]) * (w[2k2], w[2k2+1])
// xs chunks XOR-swizzled to kill the stride-16-word bank hotspot.
// ---------------------------------------------------------------------------
__global__ __launch_bounds__(256, 2) void conv_kernel(const float* __restrict__ x) {
    __shared__ __align__(16) float xs[8][272];       // 8 ci rows, 256 data + zero pad
    __shared__ __align__(16) float ws[64][8][16];    // [co][ci_local][k]
    int b = blockIdx.x;
    int tid = threadIdx.x;
    int tx = tid & 15, ty = tid >> 4;
    unsigned long long acc[4][4];
    #pragma unroll
    for (int i = 0; i < 4; i++)
        #pragma unroll
        for (int j = 0; j < 4; j++) acc[i][j] = 0ULL;

    const float* xb = x + (size_t)b * CIN * LIN;

    for (int ci0 = 0; ci0 < CIN; ci0 += 8) {
        // fill xs (zero-pad cols 256..271), swizzled at 16B-chunk granularity
        for (int g = tid; g < 544; g += 256) {      // 8 rows * 68 chunks
            int row = g / 68, c4 = g % 68;
            float4 v = make_float4(0.f, 0.f, 0.f, 0.f);
            if (c4 < 64) v = *(const float4*)(xb + (size_t)(ci0 + row) * LIN + c4 * 4);
            int sc = c4 ^ ((c4 >> 3) & 7);
            *(float4*)&xs[row][sc * 4] = v;
        }
        // fill ws: 64co * 8ci * 16k = 2048 float4
        for (int g = tid; g < 2048; g += 256) {
            int co = g >> 5, rem = g & 31, ci = rem >> 2, k4 = rem & 3;
            *(float4*)&ws[co][ci][k4 * 4] =
                *(const float4*)(g_weff + (size_t)co * (CIN * KSZ) + (ci0 + ci) * KSZ + k4 * 4);
        }
        __syncthreads();

        #pragma unroll
        for (int ci = 0; ci < 8; ci++) {
            unsigned long long xv[14];  // pairs (p, p+1) at p = 16*tx + 2*m
            #pragma unroll
            for (int j = 0; j < 7; j++) {
                int c = 4 * tx + j;
                int sc = c ^ ((c >> 3) & 7);
                ulonglong2 v = *(const ulonglong2*)&xs[ci][sc * 4];
                xv[2 * j] = v.x; xv[2 * j + 1] = v.y;
            }
            #pragma unroll
            for (int cq = 0; cq < 4; cq++) {
                unsigned long long wv[8];  // pairs (w[2k2], w[2k2+1])
                #pragma unroll
                for (int j = 0; j < 4; j++) {
                    ulonglong2 v = *(const ulonglong2*)&ws[ty * 4 + cq][ci][4 * j];
                    wv[2 * j] = v.x; wv[2 * j + 1] = v.y;
                }
                #pragma unroll
                for (int li = 0; li < 4; li++)
                    #pragma unroll
                    for (int k2 = 0; k2 < 8; k2++)
                        FMA2(acc[cq][li], xv[2 * li + k2], wv[k2]);
            }
        }
        __syncthreads();
    }

    #pragma unroll
    for (int cq = 0; cq < 4; cq++)
        #pragma unroll
        for (int li = 0; li < 4; li++) {
            int co = ty * 4 + cq, l = tx * 4 + li;
            float2 f; memcpy(&f, &acc[cq][li], 8);
            float v = f.x + f.y + g_cbias[co];
            v = fmaxf(v, 0.f);
            if (l < LOUTD) g_z[(size_t)b * FLATD + co * LOUTD + l] = v;
        }
}

// ---------------------------------------------------------------------------
// feats = g_z @ g_Wc^T + g_bc, then out[b,i,c] = feats*bit_w[i,c] + bit_b[i,c]
// grid 128 (b-tile 16), block 256; thread = 2b x 4i (i = tx + 32*iq), K-packed FFMA2
// ---------------------------------------------------------------------------
__global__ __launch_bounds__(256) void fc_kernel(const float* __restrict__ bw,
                                                 const float* __restrict__ bbias,
                                                 float* __restrict__ out) {
    __shared__ __align__(16) float zs[16][68];
    __shared__ __align__(16) float wcs[128][68];
    int b0 = blockIdx.x * 16;
    int tid = threadIdx.x, tx = tid & 31, ty = tid >> 5;
    unsigned long long acc[2][4] = {{0ULL,0ULL,0ULL,0ULL},{0ULL,0ULL,0ULL,0ULL}};

    for (int k0 = 0; k0 < FLATD; k0 += 64) {   // 61 chunks exactly
        {
            int r = tid >> 4, c4 = tid & 15;
            *(float4*)&zs[r][c4 * 4] =
                *(const float4*)(g_z + (size_t)(b0 + r) * FLATD + k0 + c4 * 4);
        }
        for (int g = tid; g < 2048; g += 256) {
            int r = g >> 4, c4 = g & 15;
            *(float4*)&wcs[r][c4 * 4] =
                *(const float4*)(g_Wc + (size_t)r * FLATD + k0 + c4 * 4);
        }
        __syncthreads();
        #pragma unroll
        for (int k4 = 0; k4 < 16; k4++) {
            ulonglong2 z0 = *(const ulonglong2*)&zs[ty * 2 + 0][k4 * 4];
            ulonglong2 z1 = *(const ulonglong2*)&zs[ty * 2 + 1][k4 * 4];
            #pragma unroll
            for (int iq = 0; iq < 4; iq++) {
                ulonglong2 w = *(const ulonglong2*)&wcs[tx + 32 * iq][k4 * 4];
                FMA2(acc[0][iq], z0.x, w.x); FMA2(acc[0][iq], z0.y, w.y);
                FMA2(acc[1][iq], z1.x, w.x); FMA2(acc[1][iq], z1.y, w.y);
            }
        }
        __syncthreads();
    }

    #pragma unroll
    for (int bq = 0; bq < 2; bq++)
        #pragma unroll
        for (int iq = 0; iq < 4; iq++) {
            int b = b0 + ty * 2 + bq, i = tx + 32 * iq;
            float2 f; memcpy(&f, &acc[bq][iq], 8);
            float feat = f.x + f.y + g_bc[i];
            out[((size_t)b * H2D + i) * 2 + 0] = feat * bw[i * 2 + 0] + bbias[i * 2 + 0];
            out[((size_t)b * H2D + i) * 2 + 1] = feat * bw[i * 2 + 1] + bbias[i * 2 + 1];
        }
}

// ---------------------------------------------------------------------------
extern "C" void kernel_launch(void* const* d_in, const int* in_sizes, int n_in,
                              void* d_out, int out_size) {
    const float* x      = (const float*)d_in[0];
    const float* conv_w = (const float*)d_in[1];
    const float* conv_b = (const float*)d_in[2];
    const float* gamma  = (const float*)d_in[3];
    const float* beta   = (const float*)d_in[4];
    const float* mean   = (const float*)d_in[5];
    const float* var    = (const float*)d_in[6];
    const float* f1w    = (const float*)d_in[7];
    const float* f1b    = (const float*)d_in[8];
    const float* f2w    = (const float*)d_in[9];
    const float* f2b    = (const float*)d_in[10];
    const float* bw     = (const float*)d_in[11];
    const float* bb     = (const float*)d_in[12];
    float* out = (float*)d_out;

    prep_conv<<<(COUT * CIN * KSZ + 255) / 256, 256>>>(conv_w, conv_b, gamma, beta, mean, var);
    dim3 cg(61, 2);
    combine_fc<<<cg, 256>>>(f1w, f2w);
    bias_fc<<<1, 128>>>(f2w, f1b, f2b);
    conv_kernel<<<BB, 256>>>(x);
    fc_kernel<<<BB / 16, 256>>>(bw, bb, out);
}

// round 4
// speedup vs baseline: 1.8189x; 1.8189x over previous
#include <cuda_runtime.h>
#include <cuda_bf16.h>
#include <cstring>
#include <cstdint>

#define BB    2048
#define CIN   256
#define LIN   256
#define COUT  64
#define KSZ   16
#define LOUTD 61
#define FLATD 3904   // 64*61
#define H1D   512
#define H2D   128
#define KTOT  4096   // CIN*KSZ

// ---- scratch (device globals; no allocation allowed) ----
__device__ float g_cbias[COUT];                   // BN-folded conv bias
__device__ float g_Wc[H2D * FLATD];               // fc2_w @ fc1_w   [128][3904]
__device__ float g_bc[H2D];                       // fc2_w @ fc1_b + fc2_b
__device__ float g_z[(size_t)BB * FLATD];         // conv+relu output [B][3904]
__device__ __align__(16) __nv_bfloat16 g_wh[COUT * KTOT];  // BN-folded W, bf16 hi
__device__ __align__(16) __nv_bfloat16 g_wl[COUT * KTOT];  // bf16 lo

// packed fp32x2 FMA (PTX-only)
#define FMA2(acc, a, b) asm("fma.rn.f32x2 %0, %1, %2, %0;" : "+l"(acc) : "l"(a), "l"(b))

// classic tensor-core mma (sm_80+ PTX; works on plain sm_103 target)
#define MMA_BF16(c, a0, a1, a2, a3, b0, b1) \
    asm volatile("mma.sync.aligned.m16n8k16.row.col.f32.bf16.bf16.f32 " \
        "{%0,%1,%2,%3}, {%4,%5,%6,%7}, {%8,%9}, {%0,%1,%2,%3};" \
        : "+f"((c)[0]), "+f"((c)[1]), "+f"((c)[2]), "+f"((c)[3]) \
        : "r"(a0), "r"(a1), "r"(a2), "r"(a3), "r"(b0), "r"(b1))

static __device__ __forceinline__ uint32_t swz(uint32_t byte) {
    return byte ^ ((byte >> 3) & 0x70);
}
__device__ __forceinline__ void cvt_pair(float a, float b, uint32_t& hp, uint32_t& lp) {
    __nv_bfloat16 h0 = __float2bfloat16_rn(a), h1 = __float2bfloat16_rn(b);
    hp = ((uint32_t)__bfloat16_as_ushort(h1) << 16) | __bfloat16_as_ushort(h0);
    float r0 = a - __bfloat162float(h0), r1 = b - __bfloat162float(h1);
    __nv_bfloat16 l0 = __float2bfloat16_rn(r0), l1 = __float2bfloat16_rn(r1);
    lp = ((uint32_t)__bfloat16_as_ushort(l1) << 16) | __bfloat16_as_ushort(l0);
}

// smem layout (bytes)
#define S_CB    0           // 64 floats (cbias)
#define S_STG   256         // stg[8 warps][2 mats][144 u32] = 9216B
#define S_AHI   10240       // [128 m][64 k] bf16 = 16384
#define S_ALO   26624
#define S_WHI   43008       // [64 n][64 k] bf16 = 8192
#define S_WLO   51200
#define S_TOTAL 59392

// ---------------------------------------------------------------------------
// Prep 1: fold BN into conv weights (split bf16, [co][k] K-major) + bias
// ---------------------------------------------------------------------------
__global__ void prep_conv(const float* __restrict__ w, const float* __restrict__ cb,
                          const float* __restrict__ gamma, const float* __restrict__ beta,
                          const float* __restrict__ mean, const float* __restrict__ var) {
    int idx = blockIdx.x * blockDim.x + threadIdx.x;
    if (idx < COUT * KTOT) {
        int co = idx >> 12;
        float inv = gamma[co] * rsqrtf(var[co] + 1e-5f);
        float we = w[idx] * inv;
        __nv_bfloat16 h = __float2bfloat16_rn(we);
        g_wh[idx] = h;
        g_wl[idx] = __float2bfloat16_rn(we - __bfloat162float(h));
    }
    if (idx < COUT) {
        float inv = gamma[idx] * rsqrtf(var[idx] + 1e-5f);
        g_cbias[idx] = (cb[idx] - mean[idx]) * inv + beta[idx];
    }
}

// ---------------------------------------------------------------------------
// Prep 2: Wc = fc2_w @ fc1_w   (verified in R2)
// ---------------------------------------------------------------------------
__global__ __launch_bounds__(256) void combine_fc(const float* __restrict__ f1w,
                                                  const float* __restrict__ f2w) {
    __shared__ __align__(16) float a_s[64][33];
    __shared__ __align__(16) float b_s[32][68];
    int j0 = blockIdx.x * 64, i0 = blockIdx.y * 64;
    int tid = threadIdx.x, tx = tid & 15, ty = tid >> 4;
    float acc[4][4] = {};
    for (int h0 = 0; h0 < H1D; h0 += 32) {
        for (int g = tid; g < 2048; g += 256) {
            int r = g >> 5, c = g & 31;
            a_s[r][c] = f2w[(size_t)(i0 + r) * H1D + h0 + c];
        }
        for (int g = tid; g < 512; g += 256) {
            int r = g >> 4, c4 = g & 15;
            *(float4*)&b_s[r][c4 * 4] =
                *(const float4*)(f1w + (size_t)(h0 + r) * FLATD + j0 + c4 * 4);
        }
        __syncthreads();
        #pragma unroll
        for (int h = 0; h < 32; h++) {
            float av[4], bv[4];
            #pragma unroll
            for (int iq = 0; iq < 4; iq++) av[iq] = a_s[ty * 4 + iq][h];
            #pragma unroll
            for (int jq = 0; jq < 4; jq++) bv[jq] = b_s[h][tx * 4 + jq];
            #pragma unroll
            for (int iq = 0; iq < 4; iq++)
                #pragma unroll
                for (int jq = 0; jq < 4; jq++) acc[iq][jq] += av[iq] * bv[jq];
        }
        __syncthreads();
    }
    #pragma unroll
    for (int iq = 0; iq < 4; iq++)
        #pragma unroll
        for (int jq = 0; jq < 4; jq++)
            g_Wc[(size_t)(i0 + ty * 4 + iq) * FLATD + j0 + tx * 4 + jq] = acc[iq][jq];
}

__global__ void bias_fc(const float* __restrict__ f2w, const float* __restrict__ f1b,
                        const float* __restrict__ f2b) {
    int i = threadIdx.x;
    float s = f2b[i];
    for (int h = 0; h < H1D; h++) s += f2w[(size_t)i * H1D + h] * f1b[h];
    g_bc[i] = s;
}

// ---------------------------------------------------------------------------
// Conv via mma.sync bf16 split hi/lo (3 passes, shared fp32 acc).
// CTA = 2 batch samples: D[m=(b,l) 128][n=co 64], K=4096 in 64-wide chunks.
// 8 warps: producer (all) + consumer 4x2 warp grid, warp tile 32m x 32n.
// ---------------------------------------------------------------------------
__global__ __launch_bounds__(256, 2)
void conv_mma(const float* __restrict__ x) {
    extern __shared__ char smem[];
    int tid = threadIdx.x, w = tid >> 5, lane = tid & 31;
    int b0 = blockIdx.x * 2;
    int b_l = w >> 2, cis = w & 3;           // producer role
    int m0 = (w & 3) * 32, n0 = (w >> 2) * 32;  // consumer role
    int g = lane >> 2, t = lane & 3;

    if (tid < 64) *(float*)(smem + S_CB + tid * 4) = g_cbias[tid];
    if (lane < 16) {  // zero staging pad entries [128..143] for both mats
        *(uint32_t*)(smem + S_STG + ((w * 2 + 0) * 144 + 128 + lane) * 4) = 0;
        *(uint32_t*)(smem + S_STG + ((w * 2 + 1) * 144 + 128 + lane) * 4) = 0;
    }

    float acc[2][4][4] = {};
    const uint4* whp = (const uint4*)g_wh;
    const uint4* wlp = (const uint4*)g_wl;

    for (int c = 0; c < 64; c++) {
        // ---- prefetch (gmem latency overlaps previous chunk's MMA) ----
        const float4* xp = (const float4*)(x + ((size_t)(b0 + b_l) * CIN + 4 * c + cis) * LIN);
        float4 xv0 = __ldg(xp + lane);
        float4 xv1 = __ldg(xp + lane + 32);
        int t0 = tid, t1 = tid + 256;
        int nn0 = t0 >> 3, q0 = t0 & 7, nn1 = t1 >> 3, q1 = t1 & 7;
        uint4 wh0 = __ldg(whp + nn0 * 512 + c * 8 + q0);
        uint4 wl0 = __ldg(wlp + nn0 * 512 + c * 8 + q0);
        uint4 wh1 = __ldg(whp + nn1 * 512 + c * 8 + q1);
        uint4 wl1 = __ldg(wlp + nn1 * 512 + c * 8 + q1);

        __syncthreads();   // consumers of chunk c-1 done with smem

        // ---- W tiles: straight copy (pre-split bf16), SW128 swizzled ----
        {
            uint32_t d0 = nn0 * 128 + q0 * 16, d1 = nn1 * 128 + q1 * 16;
            *(uint4*)(smem + S_WHI + swz(d0)) = wh0;
            *(uint4*)(smem + S_WLO + swz(d0)) = wl0;
            *(uint4*)(smem + S_WHI + swz(d1)) = wh1;
            *(uint4*)(smem + S_WLO + swz(d1)) = wl1;
        }
        // ---- split x into per-warp staging ----
        {
            uint32_t h0, l0, h1, l1;
            char* sh = smem + S_STG + ((w * 2 + 0) * 144) * 4;
            char* sl = smem + S_STG + ((w * 2 + 1) * 144) * 4;
            cvt_pair(xv0.x, xv0.y, h0, l0); cvt_pair(xv0.z, xv0.w, h1, l1);
            *(uint2*)(sh + (2 * lane) * 4) = make_uint2(h0, h1);
            *(uint2*)(sl + (2 * lane) * 4) = make_uint2(l0, l1);
            cvt_pair(xv1.x, xv1.y, h0, l0); cvt_pair(xv1.z, xv1.w, h1, l1);
            *(uint2*)(sh + (64 + 2 * lane) * 4) = make_uint2(h0, h1);
            *(uint2*)(sl + (64 + 2 * lane) * 4) = make_uint2(l0, l1);
        }
        __syncwarp();
        // ---- im2col scatter: A[m=64*b_l+l][k=16*cis+2j(+1)] = x[4l+2j(+1)] ----
        {
            const uint32_t* sh = (const uint32_t*)(smem + S_STG + ((w * 2 + 0) * 144) * 4);
            const uint32_t* sl = (const uint32_t*)(smem + S_STG + ((w * 2 + 1) * 144) * 4);
            #pragma unroll
            for (int it = 0; it < 16; it++) {
                int idx = lane + 32 * it;
                int l = idx >> 3, j = idx & 7;
                uint32_t byte = (uint32_t)(b_l * 64 + l) * 128 + (cis * 8 + j) * 4;
                uint32_t sw = swz(byte);
                *(uint32_t*)(smem + S_AHI + sw) = sh[2 * l + j];
                *(uint32_t*)(smem + S_ALO + sw) = sl[2 * l + j];
            }
        }
        __syncthreads();

        // ---- consume: 4 k-steps, 3 passes (hh, hl, lh) into shared fp32 acc ----
        #pragma unroll
        for (int ks = 0; ks < 4; ks++) {
            int k0 = ks * 16;
            uint32_t bh[4][2], bl[4][2];
            #pragma unroll
            for (int nt = 0; nt < 4; nt++) {
                int n = n0 + nt * 8 + g;
                uint32_t o0 = swz((uint32_t)n * 128 + (k0 + 2 * t) * 2);
                uint32_t o1 = swz((uint32_t)n * 128 + (k0 + 2 * t + 8) * 2);
                bh[nt][0] = *(const uint32_t*)(smem + S_WHI + o0);
                bh[nt][1] = *(const uint32_t*)(smem + S_WHI + o1);
                bl[nt][0] = *(const uint32_t*)(smem + S_WLO + o0);
                bl[nt][1] = *(const uint32_t*)(smem + S_WLO + o1);
            }
            #pragma unroll
            for (int mt = 0; mt < 2; mt++) {
                int m = m0 + mt * 16 + g;
                uint32_t o00 = swz((uint32_t)m * 128 + (k0 + 2 * t) * 2);
                uint32_t o10 = swz((uint32_t)(m + 8) * 128 + (k0 + 2 * t) * 2);
                uint32_t o01 = swz((uint32_t)m * 128 + (k0 + 2 * t + 8) * 2);
                uint32_t o11 = swz((uint32_t)(m + 8) * 128 + (k0 + 2 * t + 8) * 2);
                uint32_t ah0 = *(const uint32_t*)(smem + S_AHI + o00);
                uint32_t ah1 = *(const uint32_t*)(smem + S_AHI + o10);
                uint32_t ah2 = *(const uint32_t*)(smem + S_AHI + o01);
                uint32_t ah3 = *(const uint32_t*)(smem + S_AHI + o11);
                uint32_t al0 = *(const uint32_t*)(smem + S_ALO + o00);
                uint32_t al1 = *(const uint32_t*)(smem + S_ALO + o10);
                uint32_t al2 = *(const uint32_t*)(smem + S_ALO + o01);
                uint32_t al3 = *(const uint32_t*)(smem + S_ALO + o11);
                #pragma unroll
                for (int nt = 0; nt < 4; nt++) {
                    MMA_BF16(acc[mt][nt], ah0, ah1, ah2, ah3, bh[nt][0], bh[nt][1]);
                    MMA_BF16(acc[mt][nt], ah0, ah1, ah2, ah3, bl[nt][0], bl[nt][1]);
                    MMA_BF16(acc[mt][nt], al0, al1, al2, al3, bh[nt][0], bh[nt][1]);
                }
            }
        }
    }

    // ---- epilogue: bias + relu + store to g_z[b][co*61+l] ----
    #pragma unroll
    for (int mt = 0; mt < 2; mt++) {
        #pragma unroll
        for (int half = 0; half < 2; half++) {
            int row = m0 + mt * 16 + g + half * 8;
            int bl_ = row >> 6, l = row & 63;
            if (l < LOUTD) {
                float* zr = g_z + (size_t)(b0 + bl_) * FLATD + l;
                #pragma unroll
                for (int nt = 0; nt < 4; nt++) {
                    int co = n0 + nt * 8 + 2 * t;
                    float v0 = acc[mt][nt][half * 2 + 0] + *(const float*)(smem + S_CB + co * 4);
                    float v1 = acc[mt][nt][half * 2 + 1] + *(const float*)(smem + S_CB + (co + 1) * 4);
                    zr[co * LOUTD] = fmaxf(v0, 0.f);
                    zr[(co + 1) * LOUTD] = fmaxf(v1, 0.f);
                }
            }
        }
    }
}

// ---------------------------------------------------------------------------
// feats = g_z @ g_Wc^T + g_bc; out[b,i,c] = feats*bit_w + bit_b  (verified R2)
// ---------------------------------------------------------------------------
__global__ __launch_bounds__(256) void fc_kernel(const float* __restrict__ bw,
                                                 const float* __restrict__ bbias,
                                                 float* __restrict__ out) {
    __shared__ __align__(16) float zs[16][68];
    __shared__ __align__(16) float wcs[128][68];
    int b0 = blockIdx.x * 16;
    int tid = threadIdx.x, tx = tid & 31, ty = tid >> 5;
    unsigned long long acc[2][4] = {{0ULL,0ULL,0ULL,0ULL},{0ULL,0ULL,0ULL,0ULL}};

    for (int k0 = 0; k0 < FLATD; k0 += 64) {
        {
            int r = tid >> 4, c4 = tid & 15;
            *(float4*)&zs[r][c4 * 4] =
                *(const float4*)(g_z + (size_t)(b0 + r) * FLATD + k0 + c4 * 4);
        }
        for (int g = tid; g < 2048; g += 256) {
            int r = g >> 4, c4 = g & 15;
            *(float4*)&wcs[r][c4 * 4] =
                *(const float4*)(g_Wc + (size_t)r * FLATD + k0 + c4 * 4);
        }
        __syncthreads();
        #pragma unroll
        for (int k4 = 0; k4 < 16; k4++) {
            ulonglong2 z0 = *(const ulonglong2*)&zs[ty * 2 + 0][k4 * 4];
            ulonglong2 z1 = *(const ulonglong2*)&zs[ty * 2 + 1][k4 * 4];
            #pragma unroll
            for (int iq = 0; iq < 4; iq++) {
                ulonglong2 wv = *(const ulonglong2*)&wcs[tx + 32 * iq][k4 * 4];
                FMA2(acc[0][iq], z0.x, wv.x); FMA2(acc[0][iq], z0.y, wv.y);
                FMA2(acc[1][iq], z1.x, wv.x); FMA2(acc[1][iq], z1.y, wv.y);
            }
        }
        __syncthreads();
    }

    #pragma unroll
    for (int bq = 0; bq < 2; bq++)
        #pragma unroll
        for (int iq = 0; iq < 4; iq++) {
            int b = b0 + ty * 2 + bq, i = tx + 32 * iq;
            float2 f; memcpy(&f, &acc[bq][iq], 8);
            float feat = f.x + f.y + g_bc[i];
            out[((size_t)b * H2D + i) * 2 + 0] = feat * bw[i * 2 + 0] + bbias[i * 2 + 0];
            out[((size_t)b * H2D + i) * 2 + 1] = feat * bw[i * 2 + 1] + bbias[i * 2 + 1];
        }
}

// ---------------------------------------------------------------------------
extern "C" void kernel_launch(void* const* d_in, const int* in_sizes, int n_in,
                              void* d_out, int out_size) {
    const float* x      = (const float*)d_in[0];
    const float* conv_w = (const float*)d_in[1];
    const float* conv_b = (const float*)d_in[2];
    const float* gamma  = (const float*)d_in[3];
    const float* beta   = (const float*)d_in[4];
    const float* mean   = (const float*)d_in[5];
    const float* var    = (const float*)d_in[6];
    const float* f1w    = (const float*)d_in[7];
    const float* f1b    = (const float*)d_in[8];
    const float* f2w    = (const float*)d_in[9];
    const float* f2b    = (const float*)d_in[10];
    const float* bw     = (const float*)d_in[11];
    const float* bb     = (const float*)d_in[12];
    float* out = (float*)d_out;

    static int attr_done = 0;
    if (!attr_done) {
        cudaFuncSetAttribute(conv_mma, cudaFuncAttributeMaxDynamicSharedMemorySize, S_TOTAL);
        attr_done = 1;
    }

    prep_conv<<<(COUT * KTOT + 255) / 256, 256>>>(conv_w, conv_b, gamma, beta, mean, var);
    dim3 cg(61, 2);
    combine_fc<<<cg, 256>>>(f1w, f2w);
    bias_fc<<<1, 128>>>(f2w, f1b, f2b);
    conv_mma<<<BB / 2, 256, S_TOTAL>>>(x);
    fc_kernel<<<BB / 16, 256>>>(bw, bb, out);
}